// round 14
// baseline (speedup 1.0000x reference)
#include <cuda_runtime.h>
#include <cuda_fp16.h>
#include <cstdint>
#include <cstddef>

#define N_NODES 50000
#define N_PAD   50048                        // pad to multiple of 128
#define N_EDGES 640000
#define N_REL   8
#define CH      128
#define CAP     64

// Static device scratch (sanctioned no-cudaMalloc route)
__device__ int    g_cnt[N_NODES];                    // per-dest-row edge count
__device__ int    g_bucket[(size_t)N_NODES * CAP];   // keys: t*N_NODES+col
__device__ __half g_wh[N_REL * CH * CH];             // W fp16 [r][k][n]
__device__ __half g_xh[(size_t)N_PAD * CH];          // x fp16 (12.8MB)
__device__ __half g_xt[(size_t)N_REL * N_NODES * CH];// xt fp16, 102.4MB

// Block-transposed buckets: 32-bin blocks, each pos-level one 128B line.
__device__ __forceinline__ size_t bucket_addr(int bin, int pos) {
    return (size_t)(bin >> 5) * (CAP * 32) + (size_t)pos * 32 + (bin & 31);
}

// ---------------------------------------------------------------------------
// helpers
// ---------------------------------------------------------------------------
__device__ __forceinline__ uint32_t smem_u32(const void* p) {
    uint32_t a;
    asm("{ .reg .u64 t; cvta.to.shared.u64 t, %1; cvt.u32.u64 %0, t; }" : "=r"(a) : "l"(p));
    return a;
}

__device__ __forceinline__ void cp_async16(uint32_t smem, const void* gmem) {
    asm volatile("cp.async.cg.shared.global [%0], [%1], 16;" :: "r"(smem), "l"(gmem));
}

__device__ __forceinline__ void cp_async_wait_all() {
    asm volatile("cp.async.commit_group;\n\tcp.async.wait_group 0;" ::: "memory");
}

__device__ __forceinline__ void ldsm_x4(uint32_t* r, uint32_t addr) {
    asm volatile("ldmatrix.sync.aligned.m8n8.x4.shared.b16 {%0,%1,%2,%3}, [%4];"
                 : "=r"(r[0]), "=r"(r[1]), "=r"(r[2]), "=r"(r[3]) : "r"(addr));
}

__device__ __forceinline__ void ldsm_x4_t(uint32_t* r, uint32_t addr) {
    asm volatile("ldmatrix.sync.aligned.m8n8.x4.trans.shared.b16 {%0,%1,%2,%3}, [%4];"
                 : "=r"(r[0]), "=r"(r[1]), "=r"(r[2]), "=r"(r[3]) : "r"(addr));
}

__device__ __forceinline__ void mma_f16(float* d, const uint32_t* a, const uint32_t* b) {
    asm volatile(
        "mma.sync.aligned.m16n8k16.row.col.f32.f16.f16.f32 "
        "{%0,%1,%2,%3}, {%4,%5,%6,%7}, {%8,%9}, {%0,%1,%2,%3};"
        : "+f"(d[0]), "+f"(d[1]), "+f"(d[2]), "+f"(d[3])
        : "r"(a[0]), "r"(a[1]), "r"(a[2]), "r"(a[3]), "r"(b[0]), "r"(b[1]));
}

// ---------------------------------------------------------------------------
// launch 0: zero per-row counters
// ---------------------------------------------------------------------------
__global__ __launch_bounds__(256) void zero_cnt_kernel() {
    int i = blockIdx.x * 256 + threadIdx.x;
    if (i < N_NODES) g_cnt[i] = 0;
}

// ---------------------------------------------------------------------------
// launch 1: W -> fp16 (same [r][k][n] layout)
// ---------------------------------------------------------------------------
__global__ __launch_bounds__(256) void prep_w_kernel(const float* __restrict__ w) {
    int i = blockIdx.x * 256 + threadIdx.x;
    if (i >= N_REL * CH * CH / 4) return;
    float4 v = ((const float4*)w)[i];
    __half2 h0 = __floats2half2_rn(v.x, v.y);
    __half2 h1 = __floats2half2_rn(v.z, v.w);
    ((__half2*)g_wh)[i * 2]     = h0;
    ((__half2*)g_wh)[i * 2 + 1] = h1;
}

// ---------------------------------------------------------------------------
// launch 2: x -> fp16 (rows >= N_NODES zero-padded)
// ---------------------------------------------------------------------------
__global__ __launch_bounds__(256) void prep_x_kernel(const float* __restrict__ x) {
    int i = blockIdx.x * 256 + threadIdx.x;          // float4 index
    if (i >= N_PAD * CH / 4) return;
    int row = i >> 5;
    float4 v = make_float4(0.f, 0.f, 0.f, 0.f);
    if (row < N_NODES) v = ((const float4*)x)[i];
    __half2 h0 = __floats2half2_rn(v.x, v.y);
    __half2 h1 = __floats2half2_rn(v.z, v.w);
    uint2 u;
    u.x = *reinterpret_cast<uint32_t*>(&h0);
    u.y = *reinterpret_cast<uint32_t*>(&h1);
    ((uint2*)g_xh)[i] = u;
}

// ---------------------------------------------------------------------------
// launch 3: bucket edges by dest row; 4 edges per thread (independent atomic
// chains -> MLP-4; contiguous 16B index reads stay coalesced).
// Per-row counts Poisson(12.8); P(count > 64) ~ 1e-40.
// ---------------------------------------------------------------------------
__global__ __launch_bounds__(256) void scatter_kernel(const int* __restrict__ ei,
                                                      const int* __restrict__ et,
                                                      int E) {
    int base = (blockIdx.x * 256 + threadIdx.x) * 4;
    if (base >= E) return;

    int row[4], col[4], t[4];
    #pragma unroll
    for (int j = 0; j < 4; j++) {
        int e = base + j;
        if (e < E) {
            row[j] = ei[e];
            col[j] = ei[E + e];
            t[j]   = et[e];
        } else row[j] = -1;
    }
    int pos[4];
    #pragma unroll
    for (int j = 0; j < 4; j++) {
        bool ok = row[j] >= 0 && (unsigned)row[j] < N_NODES &&
                  (unsigned)col[j] < N_NODES && (unsigned)t[j] < N_REL;
        pos[j] = ok ? atomicAdd(&g_cnt[row[j]], 1) : CAP;
    }
    #pragma unroll
    for (int j = 0; j < 4; j++)
        if (pos[j] < CAP)
            g_bucket[bucket_addr(row[j], pos[j])] = t[j] * N_NODES + col[j];
}

// ---------------------------------------------------------------------------
// launch 4: transform — xt[r] = x @ W[r].
// Grid (391, 8): one-shot CTA per (128-row tile, relation). 256 threads,
// warp tile 32x64. As/Bs loaded via cp.async.cg (GMEM->SMEM direct, no
// register round-trip), single barrier, then LDSM + m16n8k16.
// ---------------------------------------------------------------------------
#define PITCH_H  136
#define AS_BYTES (128 * PITCH_H * 2)
#define BS_BYTES (128 * PITCH_H * 2)
#define SMEM_XT  (AS_BYTES + BS_BYTES)      // 69632

__global__ __launch_bounds__(256, 2) void xt_kernel() {
    extern __shared__ char smem[];
    char* AsB = smem;
    char* BsB = smem + AS_BYTES;

    const int tid  = threadIdx.x;
    const int warp = tid >> 5;
    const int lane = tid & 31;
    const int g    = lane >> 2;
    const int tig  = lane & 3;
    const int wm   = warp & 3;               // 4 row-groups of 32
    const int wn   = warp >> 2;              // 2 col-groups of 64
    const int row0 = blockIdx.x * 128;
    const int rel  = blockIdx.y;

    const uint32_t sAs = smem_u32(AsB);
    const uint32_t sBs = smem_u32(BsB);
    const uint32_t aAddr = sAs + (uint32_t)(wm * 32 + (lane & 15)) * 272u
                               + (uint32_t)(lane >> 4) * 16u;
    const uint32_t bAddr = sBs + (uint32_t)((lane & 7) + ((lane >> 3) & 1) * 8) * 272u
                               + (uint32_t)(lane >> 4) * 16u
                               + (uint32_t)wn * 128u;

    // As: 128x128 halves from g_xh via cp.async (2048 x 16B, 8/thread)
    #pragma unroll
    for (int it = 0; it < 8; it++) {
        int idx = it * 256 + tid;            // 0..2047
        int rw  = idx >> 4;
        int c16 = idx & 15;
        cp_async16(sAs + rw * 272 + c16 * 16,
                   g_xh + (size_t)(row0 + rw) * CH + c16 * 8);
    }
    // Bs: W[rel] fp16 via cp.async (2048 x 16B, 8/thread)
    {
        const __half* src = g_wh + (size_t)rel * CH * CH;
        #pragma unroll
        for (int it = 0; it < 8; it++) {
            int idx = it * 256 + tid;
            cp_async16(sBs + (idx >> 4) * 272 + (idx & 15) * 16, src + idx * 8);
        }
    }
    cp_async_wait_all();
    __syncthreads();

    float acc[2][8][4];
    #pragma unroll
    for (int mi = 0; mi < 2; mi++)
        #pragma unroll
        for (int ni = 0; ni < 8; ni++)
            #pragma unroll
            for (int q = 0; q < 4; q++) acc[mi][ni][q] = 0.f;

    #pragma unroll
    for (int ks = 0; ks < 8; ks++) {
        uint32_t af[2][4];
        ldsm_x4(af[0], aAddr + (uint32_t)ks * 32u);
        ldsm_x4(af[1], aAddr + (uint32_t)ks * 32u + 16u * 272u);
        uint32_t bf[4][4];
        #pragma unroll
        for (int p = 0; p < 4; p++)
            ldsm_x4_t(bf[p], bAddr + (uint32_t)ks * 4352u + (uint32_t)p * 32u);
        #pragma unroll
        for (int mi = 0; mi < 2; mi++)
            #pragma unroll
            for (int p = 0; p < 4; p++) {
                mma_f16(acc[mi][p * 2],     af[mi], bf[p]);
                mma_f16(acc[mi][p * 2 + 1], af[mi], bf[p] + 2);
            }
    }

    // epilogue: xt[rel] fp16
    __half* outb = g_xt + (size_t)rel * N_NODES * CH;
    #pragma unroll
    for (int mi = 0; mi < 2; mi++) {
        int r1 = row0 + wm * 32 + mi * 16 + g;
        int r2 = r1 + 8;
        #pragma unroll
        for (int ni = 0; ni < 8; ni++) {
            int col = wn * 64 + ni * 8 + tig * 2;
            if (r1 < N_NODES) {
                __half2 h = __floats2half2_rn(acc[mi][ni][0], acc[mi][ni][1]);
                *(__half2*)(outb + (size_t)r1 * CH + col) = h;
            }
            if (r2 < N_NODES) {
                __half2 h = __floats2half2_rn(acc[mi][ni][2], acc[mi][ni][3]);
                *(__half2*)(outb + (size_t)r2 * CH + col) = h;
            }
        }
    }
}

// ---------------------------------------------------------------------------
// launch 5: aggregate — warp per dest row, counted predicated loop, 8-way
// unrolled (mean cnt 12.8 -> ~2 latency rounds instead of 4).
// ---------------------------------------------------------------------------
__global__ __launch_bounds__(256) void aggregate_kernel(const float* __restrict__ bias,
                                                        float* __restrict__ out) {
    int row  = (blockIdx.x * 256 + threadIdx.x) >> 5;
    int lane = threadIdx.x & 31;
    if (row >= N_NODES) return;

    int cnt = g_cnt[row];
    if (cnt > CAP) cnt = CAP;

    float4 acc = make_float4(0.f, 0.f, 0.f, 0.f);

    #pragma unroll 1
    for (int i = 0; i < cnt; i += 8) {
        int k[8];
        #pragma unroll
        for (int j = 0; j < 8; j++)
            k[j] = (i + j < cnt) ? g_bucket[bucket_addr(row, i + j)] : -1;
        uint2 u[8];
        #pragma unroll
        for (int j = 0; j < 8; j++)
            if (k[j] >= 0)
                u[j] = *(const uint2*)(g_xt + (size_t)k[j] * CH + lane * 4);
        #pragma unroll
        for (int j = 0; j < 8; j++)
            if (k[j] >= 0) {
                __half2 h0 = *reinterpret_cast<__half2*>(&u[j].x);
                __half2 h1 = *reinterpret_cast<__half2*>(&u[j].y);
                float2 f0 = __half22float2(h0);
                float2 f1 = __half22float2(h1);
                acc.x += f0.x; acc.y += f0.y; acc.z += f1.x; acc.w += f1.y;
            }
    }

    float4 b = ((const float4*)bias)[lane];
    float4 r;
    r.x = acc.x + b.x; r.y = acc.y + b.y;
    r.z = acc.z + b.z; r.w = acc.w + b.w;
    ((float4*)(out + (size_t)row * CH))[lane] = r;
}

// ---------------------------------------------------------------------------
// kernel_launch
// inputs: x f32[50000*128], edge_index i32[2*640000], edge_type i32[640000],
//         weight f32[8*128*128], bias f32[128]
// ---------------------------------------------------------------------------
extern "C" void kernel_launch(void* const* d_in, const int* in_sizes, int n_in,
                              void* d_out, int out_size) {
    const float* x    = (const float*)d_in[0];
    const int*   ei   = (const int*)d_in[1];
    const int*   et   = (const int*)d_in[2];
    const float* w    = (const float*)d_in[3];
    const float* bias = (const float*)d_in[4];
    float* out = (float*)d_out;

    int E = in_sizes[2];
    if (E > N_EDGES) E = N_EDGES;

    cudaFuncSetAttribute(xt_kernel, cudaFuncAttributeMaxDynamicSharedMemorySize,
                         SMEM_XT);

    zero_cnt_kernel<<<(N_NODES + 255) / 256, 256>>>();                      // 0
    prep_w_kernel<<<(N_REL * CH * CH / 4 + 255) / 256, 256>>>(w);           // 1
    prep_x_kernel<<<(N_PAD * CH / 4 + 255) / 256, 256>>>(x);                // 2
    scatter_kernel<<<((E + 3) / 4 + 255) / 256, 256>>>(ei, et, E);          // 3
    dim3 tg(N_PAD / 128, N_REL);
    xt_kernel<<<tg, 256, SMEM_XT>>>();                                      // 4
    aggregate_kernel<<<(N_NODES * 32 + 255) / 256, 256>>>(bias, out);       // 5
}

// round 15
// speedup vs baseline: 1.0631x; 1.0631x over previous
#include <cuda_runtime.h>
#include <cuda_fp16.h>
#include <cstdint>
#include <cstddef>

#define N_NODES 50000
#define N_PAD   50048                        // pad to multiple of 128
#define N_EDGES 640000
#define N_REL   8
#define CH      128
#define CAP     64

// fused-prep block partition
#define ZB 196                               // zero_cnt blocks  (50000/256)
#define WB 128                               // prep_w blocks    (32768/256)
#define XB 6256                              // prep_x blocks    (1601536/256)

// fused-main block partition
#define SCAT_BLOCKS 2500                     // 640000 edges / 256
#define XT_TILES    391                      // N_PAD / 128
#define MAIN_BLOCKS (SCAT_BLOCKS + XT_TILES * N_REL)   // 2500 + 3128

// Static device scratch (sanctioned no-cudaMalloc route)
__device__ int    g_cnt[N_NODES];                    // per-dest-row edge count
__device__ int    g_bucket[(size_t)N_NODES * CAP];   // keys: t*N_NODES+col
__device__ __half g_wh[N_REL * CH * CH];             // W fp16 [r][k][n]
__device__ __half g_xh[(size_t)N_PAD * CH];          // x fp16 (12.8MB)
__device__ __half g_xt[(size_t)N_REL * N_NODES * CH];// xt fp16, 102.4MB

// Block-transposed buckets: 32-bin blocks, each pos-level one 128B line.
__device__ __forceinline__ size_t bucket_addr(int bin, int pos) {
    return (size_t)(bin >> 5) * (CAP * 32) + (size_t)pos * 32 + (bin & 31);
}

// ---------------------------------------------------------------------------
// helpers
// ---------------------------------------------------------------------------
__device__ __forceinline__ uint32_t smem_u32(const void* p) {
    uint32_t a;
    asm("{ .reg .u64 t; cvta.to.shared.u64 t, %1; cvt.u32.u64 %0, t; }" : "=r"(a) : "l"(p));
    return a;
}

__device__ __forceinline__ void ldsm_x4(uint32_t* r, uint32_t addr) {
    asm volatile("ldmatrix.sync.aligned.m8n8.x4.shared.b16 {%0,%1,%2,%3}, [%4];"
                 : "=r"(r[0]), "=r"(r[1]), "=r"(r[2]), "=r"(r[3]) : "r"(addr));
}

__device__ __forceinline__ void ldsm_x4_t(uint32_t* r, uint32_t addr) {
    asm volatile("ldmatrix.sync.aligned.m8n8.x4.trans.shared.b16 {%0,%1,%2,%3}, [%4];"
                 : "=r"(r[0]), "=r"(r[1]), "=r"(r[2]), "=r"(r[3]) : "r"(addr));
}

__device__ __forceinline__ void mma_f16(float* d, const uint32_t* a, const uint32_t* b) {
    asm volatile(
        "mma.sync.aligned.m16n8k16.row.col.f32.f16.f16.f32 "
        "{%0,%1,%2,%3}, {%4,%5,%6,%7}, {%8,%9}, {%0,%1,%2,%3};"
        : "+f"(d[0]), "+f"(d[1]), "+f"(d[2]), "+f"(d[3])
        : "r"(a[0]), "r"(a[1]), "r"(a[2]), "r"(a[3]), "r"(b[0]), "r"(b[1]));
}

// ---------------------------------------------------------------------------
// launch 0 (fused preps): zero g_cnt | W->fp16 | x->fp16   by blockIdx range
// ---------------------------------------------------------------------------
__global__ __launch_bounds__(256) void prep_kernel(const float* __restrict__ w,
                                                   const float* __restrict__ x) {
    int b = blockIdx.x;
    if (b < ZB) {
        int i = b * 256 + threadIdx.x;
        if (i < N_NODES) g_cnt[i] = 0;
        return;
    }
    b -= ZB;
    if (b < WB) {
        int i = b * 256 + threadIdx.x;          // float4 index, exact fit
        float4 v = ((const float4*)w)[i];
        __half2 h0 = __floats2half2_rn(v.x, v.y);
        __half2 h1 = __floats2half2_rn(v.z, v.w);
        ((__half2*)g_wh)[i * 2]     = h0;
        ((__half2*)g_wh)[i * 2 + 1] = h1;
        return;
    }
    b -= WB;
    {
        int i = b * 256 + threadIdx.x;          // float4 index, exact fit (XB)
        int row = i >> 5;
        float4 v = make_float4(0.f, 0.f, 0.f, 0.f);
        if (row < N_NODES) v = ((const float4*)x)[i];
        __half2 h0 = __floats2half2_rn(v.x, v.y);
        __half2 h1 = __floats2half2_rn(v.z, v.w);
        uint2 u;
        u.x = *reinterpret_cast<uint32_t*>(&h0);
        u.y = *reinterpret_cast<uint32_t*>(&h1);
        ((uint2*)g_xh)[i] = u;
    }
}

// ---------------------------------------------------------------------------
// launch 1 (fused main): scatter (blocks 0..2499) || xt GEMM (blocks 2500..)
// Independent work co-scheduled in one kernel: scatter's ~14.5us hides under
// the xt GEMM instead of serializing before it.
// ---------------------------------------------------------------------------
#define PITCH_H  136
#define AS_BYTES (128 * PITCH_H * 2)
#define BS_BYTES (128 * PITCH_H * 2)
#define SMEM_XT  (AS_BYTES + BS_BYTES)      // 69632

__global__ __launch_bounds__(256, 2) void main_kernel(const int* __restrict__ ei,
                                                      const int* __restrict__ et,
                                                      int E) {
    // ---------------- scatter part ----------------
    if (blockIdx.x < SCAT_BLOCKS) {
        int e = blockIdx.x * 256 + threadIdx.x;
        if (e >= E) return;
        int row = ei[e];
        int col = ei[E + e];
        int t   = et[e];
        if ((unsigned)row >= N_NODES || (unsigned)col >= N_NODES || (unsigned)t >= N_REL)
            return;
        int pos = atomicAdd(&g_cnt[row], 1);
        if (pos < CAP) g_bucket[bucket_addr(row, pos)] = t * N_NODES + col;
        return;
    }

    // ---------------- xt GEMM part ----------------
    extern __shared__ char smem[];
    char* AsB = smem;
    char* BsB = smem + AS_BYTES;

    const int xb   = blockIdx.x - SCAT_BLOCKS;   // 0 .. 3127
    const int rel  = xb / XT_TILES;
    const int row0 = (xb - rel * XT_TILES) * 128;

    const int tid  = threadIdx.x;
    const int warp = tid >> 5;
    const int lane = tid & 31;
    const int g    = lane >> 2;
    const int tig  = lane & 3;
    const int wm   = warp & 3;               // 4 row-groups of 32
    const int wn   = warp >> 2;              // 2 col-groups of 64

    const uint32_t sAs = smem_u32(AsB);
    const uint32_t sBs = smem_u32(BsB);
    const uint32_t aAddr = sAs + (uint32_t)(wm * 32 + (lane & 15)) * 272u
                               + (uint32_t)(lane >> 4) * 16u;
    const uint32_t bAddr = sBs + (uint32_t)((lane & 7) + ((lane >> 3) & 1) * 8) * 272u
                               + (uint32_t)(lane >> 4) * 16u
                               + (uint32_t)wn * 128u;

    // As: 128x128 halves from g_xh (2048 uint4, 8/thread)
    #pragma unroll
    for (int it = 0; it < 8; it++) {
        int idx = it * 256 + tid;            // 0..2047
        int rw  = idx >> 4;
        int c16 = idx & 15;
        uint4 v = *(const uint4*)(g_xh + (size_t)(row0 + rw) * CH + c16 * 8);
        *(uint4*)(AsB + rw * 272 + c16 * 16) = v;
    }
    // Bs: W[rel] fp16 (2048 uint4, 8/thread)
    {
        const uint4* src = (const uint4*)(g_wh + (size_t)rel * CH * CH);
        #pragma unroll
        for (int it = 0; it < 8; it++) {
            int idx = it * 256 + tid;
            uint4 v = src[idx];
            *(uint4*)(BsB + (idx >> 4) * 272 + (idx & 15) * 16) = v;
        }
    }
    __syncthreads();

    float acc[2][8][4];
    #pragma unroll
    for (int mi = 0; mi < 2; mi++)
        #pragma unroll
        for (int ni = 0; ni < 8; ni++)
            #pragma unroll
            for (int q = 0; q < 4; q++) acc[mi][ni][q] = 0.f;

    #pragma unroll
    for (int ks = 0; ks < 8; ks++) {
        uint32_t af[2][4];
        ldsm_x4(af[0], aAddr + (uint32_t)ks * 32u);
        ldsm_x4(af[1], aAddr + (uint32_t)ks * 32u + 16u * 272u);
        uint32_t bf[4][4];
        #pragma unroll
        for (int p = 0; p < 4; p++)
            ldsm_x4_t(bf[p], bAddr + (uint32_t)ks * 4352u + (uint32_t)p * 32u);
        #pragma unroll
        for (int mi = 0; mi < 2; mi++)
            #pragma unroll
            for (int p = 0; p < 4; p++) {
                mma_f16(acc[mi][p * 2],     af[mi], bf[p]);
                mma_f16(acc[mi][p * 2 + 1], af[mi], bf[p] + 2);
            }
    }

    // epilogue: xt[rel] fp16
    __half* outb = g_xt + (size_t)rel * N_NODES * CH;
    #pragma unroll
    for (int mi = 0; mi < 2; mi++) {
        int r1 = row0 + wm * 32 + mi * 16 + g;
        int r2 = r1 + 8;
        #pragma unroll
        for (int ni = 0; ni < 8; ni++) {
            int col = wn * 64 + ni * 8 + tig * 2;
            if (r1 < N_NODES) {
                __half2 h = __floats2half2_rn(acc[mi][ni][0], acc[mi][ni][1]);
                *(__half2*)(outb + (size_t)r1 * CH + col) = h;
            }
            if (r2 < N_NODES) {
                __half2 h = __floats2half2_rn(acc[mi][ni][2], acc[mi][ni][3]);
                *(__half2*)(outb + (size_t)r2 * CH + col) = h;
            }
        }
    }
}

// ---------------------------------------------------------------------------
// launch 2: aggregate — warp per dest row, counted predicated loop (4-way,
// the R13-measured best), no barriers, no atomics.
// ---------------------------------------------------------------------------
__global__ __launch_bounds__(256) void aggregate_kernel(const float* __restrict__ bias,
                                                        float* __restrict__ out) {
    int row  = (blockIdx.x * 256 + threadIdx.x) >> 5;
    int lane = threadIdx.x & 31;
    if (row >= N_NODES) return;

    int cnt = g_cnt[row];
    if (cnt > CAP) cnt = CAP;

    float4 acc = make_float4(0.f, 0.f, 0.f, 0.f);

    #pragma unroll 1
    for (int i = 0; i < cnt; i += 4) {
        int k[4];
        #pragma unroll
        for (int j = 0; j < 4; j++)
            k[j] = (i + j < cnt) ? g_bucket[bucket_addr(row, i + j)] : -1;
        uint2 u[4];
        #pragma unroll
        for (int j = 0; j < 4; j++)
            if (k[j] >= 0)
                u[j] = *(const uint2*)(g_xt + (size_t)k[j] * CH + lane * 4);
        #pragma unroll
        for (int j = 0; j < 4; j++)
            if (k[j] >= 0) {
                __half2 h0 = *reinterpret_cast<__half2*>(&u[j].x);
                __half2 h1 = *reinterpret_cast<__half2*>(&u[j].y);
                float2 f0 = __half22float2(h0);
                float2 f1 = __half22float2(h1);
                acc.x += f0.x; acc.y += f0.y; acc.z += f1.x; acc.w += f1.y;
            }
    }

    float4 b = ((const float4*)bias)[lane];
    float4 r;
    r.x = acc.x + b.x; r.y = acc.y + b.y;
    r.z = acc.z + b.z; r.w = acc.w + b.w;
    ((float4*)(out + (size_t)row * CH))[lane] = r;
}

// ---------------------------------------------------------------------------
// kernel_launch
// inputs: x f32[50000*128], edge_index i32[2*640000], edge_type i32[640000],
//         weight f32[8*128*128], bias f32[128]
// ---------------------------------------------------------------------------
extern "C" void kernel_launch(void* const* d_in, const int* in_sizes, int n_in,
                              void* d_out, int out_size) {
    const float* x    = (const float*)d_in[0];
    const int*   ei   = (const int*)d_in[1];
    const int*   et   = (const int*)d_in[2];
    const float* w    = (const float*)d_in[3];
    const float* bias = (const float*)d_in[4];
    float* out = (float*)d_out;

    int E = in_sizes[2];
    if (E > N_EDGES) E = N_EDGES;

    cudaFuncSetAttribute(main_kernel, cudaFuncAttributeMaxDynamicSharedMemorySize,
                         SMEM_XT);

    prep_kernel<<<ZB + WB + XB, 256>>>(w, x);                               // 0
    main_kernel<<<MAIN_BLOCKS, 256, SMEM_XT>>>(ei, et, E);                  // 1
    aggregate_kernel<<<(N_NODES * 32 + 255) / 256, 256>>>(bias, out);       // 2
}

// round 16
// speedup vs baseline: 1.0839x; 1.0196x over previous
#include <cuda_runtime.h>
#include <cuda_fp16.h>
#include <cstdint>
#include <cstddef>

#define N_NODES 50000
#define N_PAD   50048                        // pad to multiple of 128
#define N_EDGES 640000
#define N_REL   8
#define CH      128
#define CAP     64

// fused-prep block partition
#define ZB 196                               // zero_cnt blocks  (50000/256)
#define WB 128                               // prep_w blocks    (32768/256)
#define XB 6256                              // prep_x blocks    (1601536/256)

// fused-main: interleaved 4 scatter + 5 xt per group of 9
#define SCAT_BLOCKS 2500                     // 640000 edges / 256
#define XT_TILES    391                      // N_PAD / 128
#define XT_BLOCKS   (XT_TILES * N_REL)       // 3128
#define MAIN_GROUPS 626
#define MAIN_BLOCKS (MAIN_GROUPS * 9)        // 5634 (few tail blocks idle)

// Static device scratch (sanctioned no-cudaMalloc route)
__device__ int    g_cnt[N_NODES];                    // per-dest-row edge count
__device__ int    g_bucket[(size_t)N_NODES * CAP];   // keys: t*N_NODES+col
__device__ __half g_wh[N_REL * CH * CH];             // W fp16 [r][k][n]
__device__ __half g_xh[(size_t)N_PAD * CH];          // x fp16 (12.8MB)
__device__ __half g_xt[(size_t)N_REL * N_NODES * CH];// xt fp16, 102.4MB

// Block-transposed buckets: 32-bin blocks, each pos-level one 128B line.
__device__ __forceinline__ size_t bucket_addr(int bin, int pos) {
    return (size_t)(bin >> 5) * (CAP * 32) + (size_t)pos * 32 + (bin & 31);
}

// ---------------------------------------------------------------------------
// helpers
// ---------------------------------------------------------------------------
__device__ __forceinline__ uint32_t smem_u32(const void* p) {
    uint32_t a;
    asm("{ .reg .u64 t; cvta.to.shared.u64 t, %1; cvt.u32.u64 %0, t; }" : "=r"(a) : "l"(p));
    return a;
}

__device__ __forceinline__ void ldsm_x4(uint32_t* r, uint32_t addr) {
    asm volatile("ldmatrix.sync.aligned.m8n8.x4.shared.b16 {%0,%1,%2,%3}, [%4];"
                 : "=r"(r[0]), "=r"(r[1]), "=r"(r[2]), "=r"(r[3]) : "r"(addr));
}

__device__ __forceinline__ void ldsm_x4_t(uint32_t* r, uint32_t addr) {
    asm volatile("ldmatrix.sync.aligned.m8n8.x4.trans.shared.b16 {%0,%1,%2,%3}, [%4];"
                 : "=r"(r[0]), "=r"(r[1]), "=r"(r[2]), "=r"(r[3]) : "r"(addr));
}

__device__ __forceinline__ void mma_f16(float* d, const uint32_t* a, const uint32_t* b) {
    asm volatile(
        "mma.sync.aligned.m16n8k16.row.col.f32.f16.f16.f32 "
        "{%0,%1,%2,%3}, {%4,%5,%6,%7}, {%8,%9}, {%0,%1,%2,%3};"
        : "+f"(d[0]), "+f"(d[1]), "+f"(d[2]), "+f"(d[3])
        : "r"(a[0]), "r"(a[1]), "r"(a[2]), "r"(a[3]), "r"(b[0]), "r"(b[1]));
}

// ---------------------------------------------------------------------------
// launch 0 (fused preps): zero g_cnt | W->fp16 | x->fp16   by blockIdx range
// ---------------------------------------------------------------------------
__global__ __launch_bounds__(256) void prep_kernel(const float* __restrict__ w,
                                                   const float* __restrict__ x) {
    int b = blockIdx.x;
    if (b < ZB) {
        int i = b * 256 + threadIdx.x;
        if (i < N_NODES) g_cnt[i] = 0;
        return;
    }
    b -= ZB;
    if (b < WB) {
        int i = b * 256 + threadIdx.x;          // float4 index, exact fit
        float4 v = ((const float4*)w)[i];
        __half2 h0 = __floats2half2_rn(v.x, v.y);
        __half2 h1 = __floats2half2_rn(v.z, v.w);
        ((__half2*)g_wh)[i * 2]     = h0;
        ((__half2*)g_wh)[i * 2 + 1] = h1;
        return;
    }
    b -= WB;
    {
        int i = b * 256 + threadIdx.x;          // float4 index, exact fit (XB)
        int row = i >> 5;
        float4 v = make_float4(0.f, 0.f, 0.f, 0.f);
        if (row < N_NODES) v = ((const float4*)x)[i];
        __half2 h0 = __floats2half2_rn(v.x, v.y);
        __half2 h1 = __floats2half2_rn(v.z, v.w);
        uint2 u;
        u.x = *reinterpret_cast<uint32_t*>(&h0);
        u.y = *reinterpret_cast<uint32_t*>(&h1);
        ((uint2*)g_xh)[i] = u;
    }
}

// ---------------------------------------------------------------------------
// launch 1 (fused main): scatter || xt GEMM, INTERLEAVED 4:5 per 9-block
// group so every wave mixes latency-bound scatter with MMA-bound GEMM.
// xt blocks are tile-major (rel = xb%8) so the 8 relations sharing one
// g_xh row-tile are schedule-adjacent (hot As lines in L1/L2).
// ---------------------------------------------------------------------------
#define PITCH_H  136
#define AS_BYTES (128 * PITCH_H * 2)
#define BS_BYTES (128 * PITCH_H * 2)
#define SMEM_XT  (AS_BYTES + BS_BYTES)      // 69632

__global__ __launch_bounds__(256, 2) void main_kernel(const int* __restrict__ ei,
                                                      const int* __restrict__ et,
                                                      int E) {
    const int q = blockIdx.x / 9;
    const int rmod = blockIdx.x - q * 9;

    // ---------------- scatter part (4 of every 9 blocks) ----------------
    if (rmod < 4) {
        int sb = q * 4 + rmod;
        if (sb >= SCAT_BLOCKS) return;
        int e = sb * 256 + threadIdx.x;
        if (e >= E) return;
        int row = ei[e];
        int col = ei[E + e];
        int t   = et[e];
        if ((unsigned)row >= N_NODES || (unsigned)col >= N_NODES || (unsigned)t >= N_REL)
            return;
        int pos = atomicAdd(&g_cnt[row], 1);
        if (pos < CAP) g_bucket[bucket_addr(row, pos)] = t * N_NODES + col;
        return;
    }

    // ---------------- xt GEMM part (5 of every 9 blocks) ----------------
    const int xb = q * 5 + (rmod - 4);           // 0 .. 3129
    if (xb >= XT_BLOCKS) return;

    extern __shared__ char smem[];
    char* AsB = smem;
    char* BsB = smem + AS_BYTES;

    const int rel  = xb & 7;                     // tile-major: relations adjacent
    const int row0 = (xb >> 3) * 128;

    const int tid  = threadIdx.x;
    const int warp = tid >> 5;
    const int lane = tid & 31;
    const int g    = lane >> 2;
    const int tig  = lane & 3;
    const int wm   = warp & 3;               // 4 row-groups of 32
    const int wn   = warp >> 2;              // 2 col-groups of 64

    const uint32_t sAs = smem_u32(AsB);
    const uint32_t sBs = smem_u32(BsB);
    const uint32_t aAddr = sAs + (uint32_t)(wm * 32 + (lane & 15)) * 272u
                               + (uint32_t)(lane >> 4) * 16u;
    const uint32_t bAddr = sBs + (uint32_t)((lane & 7) + ((lane >> 3) & 1) * 8) * 272u
                               + (uint32_t)(lane >> 4) * 16u
                               + (uint32_t)wn * 128u;

    // As: 128x128 halves from g_xh (2048 uint4, 8/thread)
    #pragma unroll
    for (int it = 0; it < 8; it++) {
        int idx = it * 256 + tid;            // 0..2047
        int rw  = idx >> 4;
        int c16 = idx & 15;
        uint4 v = *(const uint4*)(g_xh + (size_t)(row0 + rw) * CH + c16 * 8);
        *(uint4*)(AsB + rw * 272 + c16 * 16) = v;
    }
    // Bs: W[rel] fp16 (2048 uint4, 8/thread)
    {
        const uint4* src = (const uint4*)(g_wh + (size_t)rel * CH * CH);
        #pragma unroll
        for (int it = 0; it < 8; it++) {
            int idx = it * 256 + tid;
            uint4 v = src[idx];
            *(uint4*)(BsB + (idx >> 4) * 272 + (idx & 15) * 16) = v;
        }
    }
    __syncthreads();

    float acc[2][8][4];
    #pragma unroll
    for (int mi = 0; mi < 2; mi++)
        #pragma unroll
        for (int ni = 0; ni < 8; ni++)
            #pragma unroll
            for (int q2 = 0; q2 < 4; q2++) acc[mi][ni][q2] = 0.f;

    #pragma unroll
    for (int ks = 0; ks < 8; ks++) {
        uint32_t af[2][4];
        ldsm_x4(af[0], aAddr + (uint32_t)ks * 32u);
        ldsm_x4(af[1], aAddr + (uint32_t)ks * 32u + 16u * 272u);
        uint32_t bf[4][4];
        #pragma unroll
        for (int p = 0; p < 4; p++)
            ldsm_x4_t(bf[p], bAddr + (uint32_t)ks * 4352u + (uint32_t)p * 32u);
        #pragma unroll
        for (int mi = 0; mi < 2; mi++)
            #pragma unroll
            for (int p = 0; p < 4; p++) {
                mma_f16(acc[mi][p * 2],     af[mi], bf[p]);
                mma_f16(acc[mi][p * 2 + 1], af[mi], bf[p] + 2);
            }
    }

    // epilogue: xt[rel] fp16
    __half* outb = g_xt + (size_t)rel * N_NODES * CH;
    #pragma unroll
    for (int mi = 0; mi < 2; mi++) {
        int r1 = row0 + wm * 32 + mi * 16 + g;
        int r2 = r1 + 8;
        #pragma unroll
        for (int ni = 0; ni < 8; ni++) {
            int col = wn * 64 + ni * 8 + tig * 2;
            if (r1 < N_NODES) {
                __half2 h = __floats2half2_rn(acc[mi][ni][0], acc[mi][ni][1]);
                *(__half2*)(outb + (size_t)r1 * CH + col) = h;
            }
            if (r2 < N_NODES) {
                __half2 h = __floats2half2_rn(acc[mi][ni][2], acc[mi][ni][3]);
                *(__half2*)(outb + (size_t)r2 * CH + col) = h;
            }
        }
    }
}

// ---------------------------------------------------------------------------
// launch 2: aggregate — warp per dest row, counted predicated loop (4-way,
// measured best), no barriers, no atomics.
// ---------------------------------------------------------------------------
__global__ __launch_bounds__(256) void aggregate_kernel(const float* __restrict__ bias,
                                                        float* __restrict__ out) {
    int row  = (blockIdx.x * 256 + threadIdx.x) >> 5;
    int lane = threadIdx.x & 31;
    if (row >= N_NODES) return;

    int cnt = g_cnt[row];
    if (cnt > CAP) cnt = CAP;

    float4 acc = make_float4(0.f, 0.f, 0.f, 0.f);

    #pragma unroll 1
    for (int i = 0; i < cnt; i += 4) {
        int k[4];
        #pragma unroll
        for (int j = 0; j < 4; j++)
            k[j] = (i + j < cnt) ? g_bucket[bucket_addr(row, i + j)] : -1;
        uint2 u[4];
        #pragma unroll
        for (int j = 0; j < 4; j++)
            if (k[j] >= 0)
                u[j] = *(const uint2*)(g_xt + (size_t)k[j] * CH + lane * 4);
        #pragma unroll
        for (int j = 0; j < 4; j++)
            if (k[j] >= 0) {
                __half2 h0 = *reinterpret_cast<__half2*>(&u[j].x);
                __half2 h1 = *reinterpret_cast<__half2*>(&u[j].y);
                float2 f0 = __half22float2(h0);
                float2 f1 = __half22float2(h1);
                acc.x += f0.x; acc.y += f0.y; acc.z += f1.x; acc.w += f1.y;
            }
    }

    float4 b = ((const float4*)bias)[lane];
    float4 r;
    r.x = acc.x + b.x; r.y = acc.y + b.y;
    r.z = acc.z + b.z; r.w = acc.w + b.w;
    ((float4*)(out + (size_t)row * CH))[lane] = r;
}

// ---------------------------------------------------------------------------
// kernel_launch
// inputs: x f32[50000*128], edge_index i32[2*640000], edge_type i32[640000],
//         weight f32[8*128*128], bias f32[128]
// ---------------------------------------------------------------------------
extern "C" void kernel_launch(void* const* d_in, const int* in_sizes, int n_in,
                              void* d_out, int out_size) {
    const float* x    = (const float*)d_in[0];
    const int*   ei   = (const int*)d_in[1];
    const int*   et   = (const int*)d_in[2];
    const float* w    = (const float*)d_in[3];
    const float* bias = (const float*)d_in[4];
    float* out = (float*)d_out;

    int E = in_sizes[2];
    if (E > N_EDGES) E = N_EDGES;

    cudaFuncSetAttribute(main_kernel, cudaFuncAttributeMaxDynamicSharedMemorySize,
                         SMEM_XT);

    prep_kernel<<<ZB + WB + XB, 256>>>(w, x);                               // 0
    main_kernel<<<MAIN_BLOCKS, 256, SMEM_XT>>>(ei, et, E);                  // 1
    aggregate_kernel<<<(N_NODES * 32 + 255) / 256, 256>>>(bias, out);       // 2
}